// round 12
// baseline (speedup 1.0000x reference)
#include <cuda_runtime.h>
#include <cuda_bf16.h>

// Problem constants (fixed by dataset: feats [8,64,32,32], N boxes)
#define B_    8
#define C_    64
#define H_    32
#define W_    32
#define HOUT  8
#define WOUT  8

#define WXP   36              // WxT row pitch (floats): 144B, 16B-aligned, bank step 4
#define OYP   36              // s_tmp oy pitch (floats)
#define CLP   296             // s_tmp channel pitch (floats): 1184B, 16B-aligned

#define FMA2(d, a, b, c) asm("fma.rn.f32x2 %0, %1, %2, %3;" : "=l"(d) : "l"(a), "l"(b), "l"(c))
#define PACK2(d, lo, hi) asm("mov.b64 %0, {%1, %2};" : "=l"(d) : "f"(lo), "f"(hi))
#define UNPK2(lo, hi, s) asm("mov.b64 {%0, %1}, %2;" : "=f"(lo), "=f"(hi) : "l"(s))

// ---------------------------------------------------------------------------
// Single fused kernel: grid (N, 2); block = one box x one 32-channel half.
// Prologue computes per-box sampling weights in smem (the former prep kernel),
// then warp-independent separable passes:
//   out[oy][ox][c] = sum_y sum_x Wy[y][oy] * Wx[x][ox] * f[c][y][x]
// Pass A interleaves 2 bin-pairs per loop (2 indep LDG.128/iter, acc=16 regs).
// ---------------------------------------------------------------------------
__global__ __launch_bounds__(256, 4)
void roi_kernel(const float* __restrict__ feats,
                const int* __restrict__ batch_idxs,
                const int* __restrict__ starts,
                const int* __restrict__ goals,
                float* __restrict__ out) {
    const int n   = blockIdx.x;
    const int h   = blockIdx.y;
    const int tid = threadIdx.x;

    __shared__ float s_Wy[H_ * 8];                 // raw [y][oy]
    __shared__ unsigned long long s_Wy2[H_ * 8];   // packed {w,w}
    __shared__ float s_WxT[8 * WXP];               // [ox][x]
    __shared__ float s_tmp[32 * CLP];              // [cl][oy][x]
    __shared__ int   s_hdr[8];                     // xc0,ncx,cse,b,ylo_pack,cnt_pack

    // --- zero weight arrays ---
    s_Wy[tid] = 0.0f;                              // 256 == 32*8
    if (tid < 8 * WXP - 256) s_WxT[256 + tid] = 0.0f;
    s_WxT[tid < 8 * WXP ? tid : 0] = 0.0f;
    __syncthreads();

    // --- per-box sample scatter (threads 0..63) ---
    if (tid < 64) {
        const float sy = (float)starts[2 * n + 0];
        const float sx = (float)starts[2 * n + 1];
        const float gy = (float)goals[2 * n + 0];
        const float gx = (float)goals[2 * n + 1];
        const float y_min = fminf(sy, gy), y_max = fmaxf(sy, gy);
        const float x_min = fminf(sx, gx), x_max = fmaxf(sx, gx);

        const float start_h = y_min - 0.5f;
        const float start_w = x_min - 0.5f;
        const float bin_h = (y_max - y_min) / (float)HOUT;
        const float bin_w = (x_max - x_min) / (float)WOUT;
        const int gh = (int)ceilf(bin_h);
        const int gw = (int)ceilf(bin_w);
        const float invc = 1.0f / (float)max(gh * gw, 1);

        const int axis = tid >> 5;            // 0 = y, 1 = x
        const int idx  = tid & 31;
        const int ph   = idx >> 2;
        const int i    = idx & 3;

        const float start  = axis ? start_w : start_h;
        const float bin_sz = axis ? bin_w  : bin_h;
        const int   grid   = axis ? gw     : gh;
        const float size   = 32.0f;

        const float g_safe = fmaxf((float)grid, 1.0f);
        const float pos    = start + (float)ph * bin_sz
                           + ((float)i + 0.5f) * (bin_sz / g_safe);
        const bool  valid  = (pos >= -1.0f) && (pos <= size) && (i < grid);
        const float p      = fminf(fmaxf(pos, 0.0f), size - 1.0f);
        const float lowf   = floorf(p);
        const int   low    = (int)lowf;
        const int   high   = min(low + 1, (int)size - 1);
        const float l      = p - lowf;
        const float vf     = valid ? 1.0f : 0.0f;

        if (axis == 0) {
            atomicAdd(&s_Wy[low  * 8 + ph], (1.0f - l) * vf * invc);
            atomicAdd(&s_Wy[high * 8 + ph], l * vf * invc);
        } else {
            atomicAdd(&s_WxT[ph * WXP + low ], (1.0f - l) * vf);
            atomicAdd(&s_WxT[ph * WXP + high], l * vf);
        }

        if (tid == 0) {
            s_hdr[2] = ((sy > gy) ? 2 : 0) + ((sx > gx) ? 1 : 0);
            s_hdr[3] = batch_idxs[n];
        }
    }
    __syncthreads();

    // --- pack Wy -> {w,w}; range detection (warps 0 and 1) ---
    {
        const float w = s_Wy[tid];
        unsigned long long pw;
        PACK2(pw, w, w);
        s_Wy2[tid] = pw;
    }
    if (tid < 32) {
        // per-bin-pair y ranges; groups {pair0,pair1} and {pair2,pair3}
        const int yr = tid;
        int ylo[4], cnt[4];
        #pragma unroll
        for (int pp = 0; pp < 4; pp++) {
            const bool nz = (s_Wy[yr * 8 + 2 * pp]     != 0.0f) ||
                            (s_Wy[yr * 8 + 2 * pp + 1] != 0.0f);
            unsigned m = __ballot_sync(0xffffffffu, nz);
            ylo[pp] = m ? (__ffs(m) - 1) : 0;
            cnt[pp] = m ? (32 - __clz(m)) - ylo[pp] : 0;
        }
        if (tid == 0) {
            const int cnt01 = max(cnt[0], cnt[1]);
            const int cnt23 = max(cnt[2], cnt[3]);
            unsigned ylop = 0;
            ylop |= (unsigned)min(ylo[0], H_ - cnt01);
            ylop |= (unsigned)min(ylo[1], H_ - cnt01) << 8;
            ylop |= (unsigned)min(ylo[2], H_ - cnt23) << 16;
            ylop |= (unsigned)min(ylo[3], H_ - cnt23) << 24;
            s_hdr[4] = (int)ylop;
            s_hdr[5] = cnt01 | (cnt23 << 8);
        }
    } else if (tid < 64) {
        const int lane = tid - 32;
        float s = 0.0f;
        #pragma unroll
        for (int ox = 0; ox < 8; ox++) s += s_WxT[ox * WXP + lane];
        unsigned m = __ballot_sync(0xffffffffu, s != 0.0f);
        if (lane == 0) {
            if (m) {
                const int x0  = __ffs(m) - 1;
                const int x1  = 32 - __clz(m);          // exclusive
                const int xc0 = x0 & ~3;
                s_hdr[0] = xc0;
                s_hdr[1] = (x1 - xc0 + 3) >> 2;
            } else { s_hdr[0] = 0; s_hdr[1] = 0; }
        }
    }
    __syncthreads();

    const int xc0  = s_hdr[0];
    const int ncx  = s_hdr[1];
    const int cse  = s_hdr[2];
    const int b    = s_hdr[3];
    const unsigned ylop = (unsigned)s_hdr[4];
    const int      cntp = s_hdr[5];

    const int warp = tid >> 5;
    const int lane = tid & 31;

    // ---- Pass A: tmp[cl][oy][x] = sum_y Wy[y][oy] * f[c][y][x] ----
    // Two loops; each interleaves 2 bin-pairs (2 independent LDG.128/iter).
    {
        const int cc = lane >> 3;             // channel within warp (0..3)
        const int xg = lane & 7;              // x group (4 floats)
        const int cl = warp * 4 + cc;
        const int c  = h * 32 + cl;

        const ulonglong2* __restrict__ fp = (const ulonglong2*)
            (feats + (size_t)(b * C_ + c) * (H_ * W_)) + xg;
        float* tp = s_tmp + cl * CLP + 4 * xg;

        #pragma unroll
        for (int g = 0; g < 2; g++) {
            const int ylA = (int)((ylop >> (g * 16))     & 0xFF);
            const int ylB = (int)((ylop >> (g * 16 + 8)) & 0xFF);
            const int cn  = (cntp >> (g * 8)) & 0xFF;

            const ulonglong2* fqA = fp + (size_t)ylA * 8;
            const ulonglong2* fqB = fp + (size_t)ylB * 8;

            unsigned long long acc[8];
            #pragma unroll
            for (int k = 0; k < 8; k++) acc[k] = 0ull;

            #pragma unroll 2
            for (int t = 0; t < cn; t++) {
                const ulonglong2 vA = __ldg(fqA + (size_t)t * 8);
                const ulonglong2 vB = __ldg(fqB + (size_t)t * 8);
                const ulonglong2 wA =
                    *(const ulonglong2*)&s_Wy2[(ylA + t) * 8 + 4 * g];      // bins 4g,4g+1
                const ulonglong2 wB =
                    *(const ulonglong2*)&s_Wy2[(ylB + t) * 8 + 4 * g + 2];  // bins 4g+2,4g+3
                FMA2(acc[0], vA.x, wA.x, acc[0]); FMA2(acc[1], vA.y, wA.x, acc[1]);
                FMA2(acc[2], vA.x, wA.y, acc[2]); FMA2(acc[3], vA.y, wA.y, acc[3]);
                FMA2(acc[4], vB.x, wB.x, acc[4]); FMA2(acc[5], vB.y, wB.x, acc[5]);
                FMA2(acc[6], vB.x, wB.y, acc[6]); FMA2(acc[7], vB.y, wB.y, acc[7]);
            }

            #pragma unroll
            for (int k = 0; k < 4; k++) {
                ulonglong2 r;
                r.x = acc[2 * k];
                r.y = acc[2 * k + 1];
                *reinterpret_cast<ulonglong2*>(tp + (4 * g + k) * OYP) = r;
            }
        }
    }
    __syncwarp();      // warp-local: pass B reads only this warp's tmp region

    // ---- Pass B: out[c][bin] = sum_x Wx[x][ox_s] * tmp[cl][oy_s][x] ----
    {
        #pragma unroll
        for (int half = 0; half < 2; half++) {
            const int bin = half * 32 + lane;
            const int py  = bin >> 3;
            const int px  = bin & 7;
            int oy_s, ox_s;                    // source bin after flip
            if      (cse == 0) { oy_s = py;     ox_s = px;     }
            else if (cse == 3) { oy_s = 7 - py; ox_s = px;     }
            else               { oy_s = py;     ox_s = 7 - py; }

            unsigned long long a2[4];
            #pragma unroll
            for (int ch = 0; ch < 4; ch++) a2[ch] = 0ull;

            const float* wrow = s_WxT + ox_s * WXP;
            const float* trow = s_tmp + (warp * 4) * CLP + oy_s * OYP;

            for (int k = 0; k < ncx; k++) {
                const int x4 = xc0 + 4 * k;
                const ulonglong2 wv = *reinterpret_cast<const ulonglong2*>(wrow + x4);
                #pragma unroll
                for (int ch = 0; ch < 4; ch++) {
                    const ulonglong2 tv =
                        *reinterpret_cast<const ulonglong2*>(trow + ch * CLP + x4);
                    FMA2(a2[ch], tv.x, wv.x, a2[ch]);
                    FMA2(a2[ch], tv.y, wv.y, a2[ch]);
                }
            }

            float* __restrict__ ob =
                out + (size_t)n * (C_ * HOUT * WOUT)
                    + (size_t)(h * 32 + warp * 4) * 64 + bin;
            #pragma unroll
            for (int ch = 0; ch < 4; ch++) {
                float lo, hi;
                UNPK2(lo, hi, a2[ch]);
                ob[(size_t)ch * 64] = lo + hi;     // 128B coalesced per (half,ch)
            }
        }
    }
}

extern "C" void kernel_launch(void* const* d_in, const int* in_sizes, int n_in,
                              void* d_out, int out_size) {
    const float* feats      = (const float*)d_in[0];
    const int*   batch_idxs = (const int*)d_in[1];
    const int*   starts     = (const int*)d_in[2];
    const int*   goals      = (const int*)d_in[3];
    float*       out        = (float*)d_out;

    const int N = in_sizes[1];   // number of boxes (1024)

    dim3 grid(N, 2);
    roi_kernel<<<grid, 256>>>(feats, batch_idxs, starts, goals, out);
}